// round 3
// baseline (speedup 1.0000x reference)
#include <cuda_runtime.h>
#include <cuda_bf16.h>
#include <cstdint>
#include <cstddef>

#define N_USERS 100000
#define N_ITEMS 50000
#define NTOT    150000
#define D       64
#define NNZ     2000000
#define BSZ     16384
#define BITW    ((NTOT + 31) / 32)

// Scratch (allocation-free rule: __device__ globals)
__device__ float    d_e1[(size_t)NTOT * D];
__device__ float    d_e2[(size_t)NTOT * D];
__device__ float    d_e3[(size_t)NTOT * D];
__device__ unsigned d_bitmap[BITW];

// ---------------------------------------------------------------------------
// Zero scratch buffers + bitmap (required every call: graph replays)
// ---------------------------------------------------------------------------
__global__ void zero_kernel() {
    unsigned i = blockIdx.x * blockDim.x + threadIdx.x;
    const unsigned n4 = (unsigned)(NTOT * D / 4);
    float4 z = make_float4(0.f, 0.f, 0.f, 0.f);
    if (i < n4) {
        reinterpret_cast<float4*>(d_e1)[i] = z;
        reinterpret_cast<float4*>(d_e2)[i] = z;
        reinterpret_cast<float4*>(d_e3)[i] = z;
    }
    if (i < BITW) d_bitmap[i] = 0u;
}

// Mark rows needed by the final gather (users and N_USERS+items)
__global__ void mark_kernel(const int* __restrict__ users,
                            const int* __restrict__ items) {
    int i = blockIdx.x * blockDim.x + threadIdx.x;
    if (i < BSZ) {
        int r = users[i];
        atomicOr(&d_bitmap[r >> 5], 1u << (r & 31));
    } else if (i < 2 * BSZ) {
        int r = N_USERS + items[i - BSZ];
        atomicOr(&d_bitmap[r >> 5], 1u << (r & 31));
    }
}

// ---------------------------------------------------------------------------
// SpMM: e_out[row] += val * e_in[col], edge-parallel, 16 lanes per edge.
// MODE 0: src = concat(emb_user, emb_item) -> d_e1
// MODE 1: d_e1 -> d_e2
// MODE 2: d_e2 -> d_e3, filtered by needed-row bitmap
// ---------------------------------------------------------------------------
template <int MODE>
__global__ void spmm_kernel(const int*   __restrict__ grow,
                            const int*   __restrict__ gcol,
                            const float* __restrict__ gval,
                            const float* __restrict__ embU,
                            const float* __restrict__ embI) {
    unsigned gid = blockIdx.x * blockDim.x + threadIdx.x;
    unsigned e   = gid >> 4;
    if (e >= NNZ) return;

    int r = __ldg(grow + e);
    if (MODE == 2) {
        if (!((d_bitmap[r >> 5] >> (r & 31)) & 1u)) return;  // row never read
    }

    unsigned c4 = (gid & 15u) << 2;       // float offset within 64-wide row
    int   cl = __ldg(gcol + e);
    float v  = __ldg(gval + e);

    const float* xp;
    if (MODE == 0) {
        xp = (cl < N_USERS) ? (embU + (size_t)cl * D)
                            : (embI + (size_t)(cl - N_USERS) * D);
    } else if (MODE == 1) {
        xp = d_e1 + (size_t)cl * D;
    } else {
        xp = d_e2 + (size_t)cl * D;
    }

    float4 x = *reinterpret_cast<const float4*>(xp + c4);

    float* dp;
    if (MODE == 0)      dp = d_e1 + (size_t)r * D + c4;
    else if (MODE == 1) dp = d_e2 + (size_t)r * D + c4;
    else                dp = d_e3 + (size_t)r * D + c4;

    // Vector L2 reduction: one 16B RMW instead of 4 scalar atomics.
    asm volatile("red.global.add.v4.f32 [%0], {%1, %2, %3, %4};"
                 :: "l"(dp), "f"(v * x.x), "f"(v * x.y),
                    "f"(v * x.z), "f"(v * x.w)
                 : "memory");
}

// ---------------------------------------------------------------------------
// Final head: gather light embeddings, W_u/W_i matvecs, softmax, sigmoid, dot.
// One thread per batch element, 64 threads/block. Shared: Wu, Wi, per-thread
// softmax scratch (exactly 48KB static).
// ---------------------------------------------------------------------------
__global__ __launch_bounds__(64) void final_kernel(
    const float* __restrict__ embU, const float* __restrict__ embI,
    const float* __restrict__ wU,   const float* __restrict__ wI,
    const float* __restrict__ x1,   const float* __restrict__ x0,
    const int*   __restrict__ users,const int*   __restrict__ items,
    const int*   __restrict__ xij,  float*       __restrict__ out) {
    __shared__ float sWu[D * D];
    __shared__ float sWi[D * D];
    __shared__ float sa[D * 64];

    int tid = threadIdx.x;
    for (int i = tid; i < D * D; i += 64) {
        sWu[i] = wU[i];
        sWi[i] = wI[i];
    }
    __syncthreads();

    int b  = blockIdx.x * 64 + tid;
    int u  = users[b];
    int it = items[b];

    float vec[D];

    // user light embedding = (e0 + e1 + e2 + e3) / 4
    {
        const float* p0 = embU + (size_t)u * D;
        const float* p1 = d_e1 + (size_t)u * D;
        const float* p2 = d_e2 + (size_t)u * D;
        const float* p3 = d_e3 + (size_t)u * D;
#pragma unroll
        for (int d = 0; d < D; d++)
            vec[d] = 0.25f * (p0[d] + p1[d] + p2[d] + p3[d]);
    }

    // a[j] = <vec, Wu[j,:]>   (ue @ w_user.T)
    float amax = -1e30f;
    for (int j = 0; j < D; j++) {
        const float* w = sWu + j * D;
        float a = 0.f;
#pragma unroll
        for (int d = 0; d < D; d++) a = fmaf(vec[d], w[d], a);
        sa[j * 64 + tid] = a;
        amax = fmaxf(amax, a);
    }
    float ssum = 0.f;
    for (int j = 0; j < D; j++) {
        float ex = __expf(sa[j * 64 + tid] - amax);
        sa[j * 64 + tid] = ex;
        ssum += ex;
    }
    float scale = 0.5f / ssum;   // (1 - hx) * softmax

    // item light embedding
    {
        size_t ir = (size_t)(N_USERS + it) * D;
        const float* q0 = embI + (size_t)it * D;
#pragma unroll
        for (int d = 0; d < D; d++)
            vec[d] = 0.25f * (q0[d] + d_e1[ir + d] + d_e2[ir + d] + d_e3[ir + d]);
    }

    float res = 0.f;
    for (int j = 0; j < D; j++) {
        const float* w = sWi + j * D;
        float a = 0.f;
#pragma unroll
        for (int d = 0; d < D; d++) a = fmaf(vec[d], w[d], a);
        float sg = 1.f / (1.f + __expf(-a));
        res += sa[j * 64 + tid] * scale * sg;
    }

    // xij column: hx * sigmoid(xij_emb)
    float xe = (xij[b] > 0) ? x1[it] : x0[it];
    res += 0.5f * (1.f / (1.f + __expf(-xe)));

    out[b] = res;
}

// ---------------------------------------------------------------------------
extern "C" void kernel_launch(void* const* d_in, const int* in_sizes, int n_in,
                              void* d_out, int out_size) {
    const float* embU  = (const float*)d_in[0];
    const float* embI  = (const float*)d_in[1];
    const float* wU    = (const float*)d_in[2];
    const float* wI    = (const float*)d_in[3];
    const float* x1    = (const float*)d_in[4];
    const float* x0    = (const float*)d_in[5];
    const float* gval  = (const float*)d_in[6];
    const int*   grow  = (const int*)d_in[7];
    const int*   gcol  = (const int*)d_in[8];
    const int*   users = (const int*)d_in[9];
    const int*   items = (const int*)d_in[10];
    const int*   xij   = (const int*)d_in[11];
    float*       out   = (float*)d_out;

    (void)in_sizes; (void)n_in; (void)out_size;

    // 1) zero scratch + bitmap
    {
        unsigned n4 = (unsigned)(NTOT * D / 4);
        zero_kernel<<<(n4 + 255) / 256, 256>>>();
    }
    // 2) mark needed rows for layer-3 pruning
    mark_kernel<<<(2 * BSZ + 255) / 256, 256>>>(users, items);

    // 3) three SpMM layers (16 lanes per edge)
    const unsigned total  = (unsigned)NNZ * 16u;
    const unsigned blocks = (total + 255) / 256;
    spmm_kernel<0><<<blocks, 256>>>(grow, gcol, gval, embU, embI);
    spmm_kernel<1><<<blocks, 256>>>(grow, gcol, gval, embU, embI);
    spmm_kernel<2><<<blocks, 256>>>(grow, gcol, gval, embU, embI);

    // 4) final head
    final_kernel<<<BSZ / 64, 64>>>(embU, embI, wU, wI, x1, x0,
                                   users, items, xij, out);
}

// round 4
// speedup vs baseline: 1.3428x; 1.3428x over previous
#include <cuda_runtime.h>
#include <cuda_bf16.h>
#include <cstdint>
#include <cstddef>

#define N_USERS 100000
#define N_ITEMS 50000
#define NTOT    150000
#define D       64
#define NNZ     2000000
#define BSZ     16384
#define BITW    ((NTOT + 31) / 32)
#define UNROLL  4
#define CHUNK   (NNZ / UNROLL)

// Scratch (allocation-free rule: __device__ globals)
__device__ float    d_e1[(size_t)NTOT * D];
__device__ float    d_e2[(size_t)NTOT * D];
__device__ float    d_e3[(size_t)NTOT * D];
__device__ unsigned d_bitmap[BITW];

// ---------------------------------------------------------------------------
// Zero scratch buffers + bitmap (required every call: graph replays)
// ---------------------------------------------------------------------------
__global__ void zero_kernel() {
    unsigned i = blockIdx.x * blockDim.x + threadIdx.x;
    const unsigned n4 = (unsigned)(NTOT * D / 4);
    float4 z = make_float4(0.f, 0.f, 0.f, 0.f);
    if (i < n4) {
        reinterpret_cast<float4*>(d_e1)[i] = z;
        reinterpret_cast<float4*>(d_e2)[i] = z;
        reinterpret_cast<float4*>(d_e3)[i] = z;
    }
    if (i < BITW) d_bitmap[i] = 0u;
}

// Mark rows needed by the final gather (users and N_USERS+items)
__global__ void mark_kernel(const int* __restrict__ users,
                            const int* __restrict__ items) {
    int i = blockIdx.x * blockDim.x + threadIdx.x;
    if (i < BSZ) {
        int r = users[i];
        atomicOr(&d_bitmap[r >> 5], 1u << (r & 31));
    } else if (i < 2 * BSZ) {
        int r = N_USERS + items[i - BSZ];
        atomicOr(&d_bitmap[r >> 5], 1u << (r & 31));
    }
}

// ---------------------------------------------------------------------------
// SpMM: e_out[row] += val * e_in[col], edge-parallel, 16 lanes per edge,
// UNROLL=4 edges per thread (strided by CHUNK so index loads coalesce).
// All 4 gathers are issued before any RED -> per-thread MLP = 4.
// MODE 0: src = concat(emb_user, emb_item) -> d_e1
// MODE 1: d_e1 -> d_e2
// MODE 2: d_e2 -> d_e3, filtered by needed-row bitmap
// ---------------------------------------------------------------------------
template <int MODE>
__global__ __launch_bounds__(256) void spmm_kernel(
        const int*   __restrict__ grow,
        const int*   __restrict__ gcol,
        const float* __restrict__ gval,
        const float* __restrict__ embU,
        const float* __restrict__ embI) {
    unsigned gid = blockIdx.x * blockDim.x + threadIdx.x;
    unsigned g   = gid >> 4;
    if (g >= CHUNK) return;
    unsigned c4 = (gid & 15u) << 2;       // float offset within 64-wide row

    int   r[UNROLL], cl[UNROLL];
    float v[UNROLL];
    bool  act[UNROLL];

#pragma unroll
    for (int k = 0; k < UNROLL; k++) {
        unsigned e = g + (unsigned)k * CHUNK;
        r[k]  = __ldg(grow + e);
        cl[k] = __ldg(gcol + e);
        v[k]  = __ldg(gval + e);
        if (MODE == 2)
            act[k] = (__ldg(&d_bitmap[r[k] >> 5]) >> (r[k] & 31)) & 1u;
        else
            act[k] = true;
    }

    float4 x[UNROLL];
#pragma unroll
    for (int k = 0; k < UNROLL; k++) {
        if (!act[k]) { x[k] = make_float4(0.f, 0.f, 0.f, 0.f); continue; }
        const float* xp;
        if (MODE == 0) {
            xp = (cl[k] < N_USERS) ? (embU + (size_t)cl[k] * D)
                                   : (embI + (size_t)(cl[k] - N_USERS) * D);
        } else if (MODE == 1) {
            xp = d_e1 + (size_t)cl[k] * D;
        } else {
            xp = d_e2 + (size_t)cl[k] * D;
        }
        x[k] = *reinterpret_cast<const float4*>(xp + c4);
    }

#pragma unroll
    for (int k = 0; k < UNROLL; k++) {
        if (!act[k]) continue;
        float* dp;
        if (MODE == 0)      dp = d_e1 + (size_t)r[k] * D + c4;
        else if (MODE == 1) dp = d_e2 + (size_t)r[k] * D + c4;
        else                dp = d_e3 + (size_t)r[k] * D + c4;
        asm volatile("red.global.add.v4.f32 [%0], {%1, %2, %3, %4};"
                     :: "l"(dp), "f"(v[k] * x[k].x), "f"(v[k] * x[k].y),
                        "f"(v[k] * x[k].z), "f"(v[k] * x[k].w)
                     : "memory");
    }
}

// ---------------------------------------------------------------------------
// Final head: gather light embeddings, W_u/W_i matvecs, softmax, sigmoid, dot.
// One thread per batch element, 64 threads/block.
// ---------------------------------------------------------------------------
__global__ __launch_bounds__(64) void final_kernel(
    const float* __restrict__ embU, const float* __restrict__ embI,
    const float* __restrict__ wU,   const float* __restrict__ wI,
    const float* __restrict__ x1,   const float* __restrict__ x0,
    const int*   __restrict__ users,const int*   __restrict__ items,
    const int*   __restrict__ xij,  float*       __restrict__ out) {
    __shared__ float sWu[D * D];
    __shared__ float sWi[D * D];
    __shared__ float sa[D * 64];

    int tid = threadIdx.x;
    for (int i = tid; i < D * D; i += 64) {
        sWu[i] = wU[i];
        sWi[i] = wI[i];
    }
    __syncthreads();

    int b  = blockIdx.x * 64 + tid;
    int u  = users[b];
    int it = items[b];

    float vec[D];

    // user light embedding = (e0 + e1 + e2 + e3) / 4
    {
        const float* p0 = embU + (size_t)u * D;
        const float* p1 = d_e1 + (size_t)u * D;
        const float* p2 = d_e2 + (size_t)u * D;
        const float* p3 = d_e3 + (size_t)u * D;
#pragma unroll
        for (int d = 0; d < D; d++)
            vec[d] = 0.25f * (p0[d] + p1[d] + p2[d] + p3[d]);
    }

    // a[j] = <vec, Wu[j,:]>   (ue @ w_user.T)
    float amax = -1e30f;
    for (int j = 0; j < D; j++) {
        const float* w = sWu + j * D;
        float a = 0.f;
#pragma unroll
        for (int d = 0; d < D; d++) a = fmaf(vec[d], w[d], a);
        sa[j * 64 + tid] = a;
        amax = fmaxf(amax, a);
    }
    float ssum = 0.f;
    for (int j = 0; j < D; j++) {
        float ex = __expf(sa[j * 64 + tid] - amax);
        sa[j * 64 + tid] = ex;
        ssum += ex;
    }
    float scale = 0.5f / ssum;   // (1 - hx) * softmax

    // item light embedding
    {
        size_t ir = (size_t)(N_USERS + it) * D;
        const float* q0 = embI + (size_t)it * D;
#pragma unroll
        for (int d = 0; d < D; d++)
            vec[d] = 0.25f * (q0[d] + d_e1[ir + d] + d_e2[ir + d] + d_e3[ir + d]);
    }

    float res = 0.f;
    for (int j = 0; j < D; j++) {
        const float* w = sWi + j * D;
        float a = 0.f;
#pragma unroll
        for (int d = 0; d < D; d++) a = fmaf(vec[d], w[d], a);
        float sg = 1.f / (1.f + __expf(-a));
        res += sa[j * 64 + tid] * scale * sg;
    }

    // xij column: hx * sigmoid(xij_emb)
    float xe = (xij[b] > 0) ? x1[it] : x0[it];
    res += 0.5f * (1.f / (1.f + __expf(-xe)));

    out[b] = res;
}

// ---------------------------------------------------------------------------
extern "C" void kernel_launch(void* const* d_in, const int* in_sizes, int n_in,
                              void* d_out, int out_size) {
    const float* embU  = (const float*)d_in[0];
    const float* embI  = (const float*)d_in[1];
    const float* wU    = (const float*)d_in[2];
    const float* wI    = (const float*)d_in[3];
    const float* x1    = (const float*)d_in[4];
    const float* x0    = (const float*)d_in[5];
    const float* gval  = (const float*)d_in[6];
    const int*   grow  = (const int*)d_in[7];
    const int*   gcol  = (const int*)d_in[8];
    const int*   users = (const int*)d_in[9];
    const int*   items = (const int*)d_in[10];
    const int*   xij   = (const int*)d_in[11];
    float*       out   = (float*)d_out;

    (void)in_sizes; (void)n_in; (void)out_size;

    // 1) zero scratch + bitmap
    {
        unsigned n4 = (unsigned)(NTOT * D / 4);
        zero_kernel<<<(n4 + 255) / 256, 256>>>();
    }
    // 2) mark needed rows for layer-3 pruning
    mark_kernel<<<(2 * BSZ + 255) / 256, 256>>>(users, items);

    // 3) three SpMM layers (16 lanes per edge, 4 edges per thread)
    const unsigned total  = (unsigned)CHUNK * 16u;
    const unsigned blocks = (total + 255) / 256;
    spmm_kernel<0><<<blocks, 256>>>(grow, gcol, gval, embU, embI);
    spmm_kernel<1><<<blocks, 256>>>(grow, gcol, gval, embU, embI);
    spmm_kernel<2><<<blocks, 256>>>(grow, gcol, gval, embU, embI);

    // 4) final head
    final_kernel<<<BSZ / 64, 64>>>(embU, embI, wU, wI, x1, x0,
                                   users, items, xij, out);
}

// round 5
// speedup vs baseline: 1.9183x; 1.4286x over previous
#include <cuda_runtime.h>
#include <cuda_bf16.h>
#include <cstdint>
#include <cstddef>

#define N_USERS 100000
#define N_ITEMS 50000
#define NTOT    150000
#define D       64
#define NNZ     2000000
#define BSZ     16384
#define BITW    ((NTOT + 31) / 32)
#define TILE    1024
#define NBLK    ((NTOT + TILE - 1) / TILE)   // 147

// Scratch (allocation-free rule: __device__ globals)
__device__ float    d_e1[(size_t)NTOT * D];
__device__ float    d_e2[(size_t)NTOT * D];
__device__ float    d_e3[(size_t)NTOT * D];
__device__ unsigned d_bitmap[BITW];
__device__ int      d_cnt[NTOT];
__device__ int      d_start[NTOT + 1];
__device__ int      d_cursor[NTOT];
__device__ int      d_bsum[NBLK];
__device__ int      d_boff[NBLK];
__device__ int2     d_epack[NNZ];            // {col, bitcast(val)}

// ---------------------------------------------------------------------------
// Zero per-row counters + bitmap (graph replays -> must reset every call)
// ---------------------------------------------------------------------------
__global__ void reset_kernel() {
    int i = blockIdx.x * blockDim.x + threadIdx.x;
    if (i < NTOT) d_cnt[i] = 0;
    if (i < BITW) d_bitmap[i] = 0u;
}

// Mark rows needed by the final gather (users and N_USERS+items)
__global__ void mark_kernel(const int* __restrict__ users,
                            const int* __restrict__ items) {
    int i = blockIdx.x * blockDim.x + threadIdx.x;
    if (i < BSZ) {
        int r = users[i];
        atomicOr(&d_bitmap[r >> 5], 1u << (r & 31));
    } else if (i < 2 * BSZ) {
        int r = N_USERS + items[i - BSZ];
        atomicOr(&d_bitmap[r >> 5], 1u << (r & 31));
    }
}

// ---------------------------------------------------------------------------
// CSR build: histogram -> scan (3 kernels) -> scatter packed {col,val}
// ---------------------------------------------------------------------------
__global__ void hist_kernel(const int* __restrict__ grow) {
    int e = blockIdx.x * blockDim.x + threadIdx.x;
    if (e < NNZ) atomicAdd(&d_cnt[grow[e]], 1);
}

// Per-block exclusive scan over TILE=1024 elements (256 thr x 4), block sums out.
__global__ __launch_bounds__(256) void scan1_kernel() {
    __shared__ int sh[256];
    int t = threadIdx.x, b = blockIdx.x;
    int base = b * TILE + t * 4;
    int v[4];
#pragma unroll
    for (int i = 0; i < 4; i++) v[i] = (base + i < NTOT) ? d_cnt[base + i] : 0;
    int s = v[0] + v[1] + v[2] + v[3];
    sh[t] = s;
    __syncthreads();
    for (int off = 1; off < 256; off <<= 1) {
        int x = (t >= off) ? sh[t - off] : 0;
        __syncthreads();
        sh[t] += x;
        __syncthreads();
    }
    int run = sh[t] - s;              // exclusive prefix of this thread
#pragma unroll
    for (int i = 0; i < 4; i++) {
        if (base + i < NTOT) d_start[base + i] = run;
        run += v[i];
    }
    if (t == 255) d_bsum[b] = sh[255];
}

// Single-block exclusive scan over the NBLK block sums.
__global__ __launch_bounds__(256) void scan2_kernel() {
    __shared__ int sh[256];
    int t = threadIdx.x;
    int v = (t < NBLK) ? d_bsum[t] : 0;
    sh[t] = v;
    __syncthreads();
    for (int off = 1; off < 256; off <<= 1) {
        int x = (t >= off) ? sh[t - off] : 0;
        __syncthreads();
        sh[t] += x;
        __syncthreads();
    }
    if (t < NBLK) d_boff[t] = sh[t] - v;
}

// Add block offsets; init cursors; write final sentinel.
__global__ void scan3_kernel() {
    int i = blockIdx.x * blockDim.x + threadIdx.x;
    if (i < NTOT) {
        int s = d_start[i] + d_boff[i / TILE];
        d_start[i]  = s;
        d_cursor[i] = s;
    }
    if (i == NTOT) d_start[NTOT] = NNZ;
}

__global__ void scatter_kernel(const int* __restrict__ grow,
                               const int* __restrict__ gcol,
                               const float* __restrict__ gval) {
    int e = blockIdx.x * blockDim.x + threadIdx.x;
    if (e < NNZ) {
        int r = grow[e];
        int p = atomicAdd(&d_cursor[r], 1);
        d_epack[p] = make_int2(gcol[e], __float_as_int(gval[e]));
    }
}

// ---------------------------------------------------------------------------
// Row-parallel SpMM over CSR: 16 lanes per row, 4-deep pipelined gather loop,
// register float4 accumulation, single STG.128 per lane. No atomics.
// MODE 0: src = concat(emb_user, emb_item) -> d_e1
// MODE 1: d_e1 -> d_e2
// MODE 2: d_e2 -> d_e3, whole rows skipped unless needed (bitmap)
// ---------------------------------------------------------------------------
template <int MODE>
__device__ __forceinline__ const float* src_row(int col,
                                                const float* __restrict__ embU,
                                                const float* __restrict__ embI) {
    if (MODE == 0)
        return (col < N_USERS) ? (embU + (size_t)col * D)
                               : (embI + (size_t)(col - N_USERS) * D);
    else if (MODE == 1)
        return d_e1 + (size_t)col * D;
    else
        return d_e2 + (size_t)col * D;
}

template <int MODE>
__global__ __launch_bounds__(256) void spmm_csr_kernel(
        const float* __restrict__ embU,
        const float* __restrict__ embI) {
    unsigned gid = blockIdx.x * blockDim.x + threadIdx.x;
    unsigned r   = gid >> 4;
    if (r >= NTOT) return;
    if (MODE == 2) {
        if (!((d_bitmap[r >> 5] >> (r & 31)) & 1u)) return;
    }
    unsigned c4 = (gid & 15u) << 2;

    int j   = __ldg(d_start + r);
    int end = __ldg(d_start + r + 1);

    float4 acc = make_float4(0.f, 0.f, 0.f, 0.f);

    // 4-deep software pipeline: 4 independent gathers in flight.
    for (; j + 4 <= end; j += 4) {
        int2 p0 = __ldg(d_epack + j);
        int2 p1 = __ldg(d_epack + j + 1);
        int2 p2 = __ldg(d_epack + j + 2);
        int2 p3 = __ldg(d_epack + j + 3);
        float4 x0 = *reinterpret_cast<const float4*>(src_row<MODE>(p0.x, embU, embI) + c4);
        float4 x1 = *reinterpret_cast<const float4*>(src_row<MODE>(p1.x, embU, embI) + c4);
        float4 x2 = *reinterpret_cast<const float4*>(src_row<MODE>(p2.x, embU, embI) + c4);
        float4 x3 = *reinterpret_cast<const float4*>(src_row<MODE>(p3.x, embU, embI) + c4);
        float v0 = __int_as_float(p0.y), v1 = __int_as_float(p1.y);
        float v2 = __int_as_float(p2.y), v3 = __int_as_float(p3.y);
        acc.x = fmaf(v0, x0.x, acc.x); acc.y = fmaf(v0, x0.y, acc.y);
        acc.z = fmaf(v0, x0.z, acc.z); acc.w = fmaf(v0, x0.w, acc.w);
        acc.x = fmaf(v1, x1.x, acc.x); acc.y = fmaf(v1, x1.y, acc.y);
        acc.z = fmaf(v1, x1.z, acc.z); acc.w = fmaf(v1, x1.w, acc.w);
        acc.x = fmaf(v2, x2.x, acc.x); acc.y = fmaf(v2, x2.y, acc.y);
        acc.z = fmaf(v2, x2.z, acc.z); acc.w = fmaf(v2, x2.w, acc.w);
        acc.x = fmaf(v3, x3.x, acc.x); acc.y = fmaf(v3, x3.y, acc.y);
        acc.z = fmaf(v3, x3.z, acc.z); acc.w = fmaf(v3, x3.w, acc.w);
    }
    for (; j < end; j++) {
        int2 p = __ldg(d_epack + j);
        float4 x = *reinterpret_cast<const float4*>(src_row<MODE>(p.x, embU, embI) + c4);
        float v = __int_as_float(p.y);
        acc.x = fmaf(v, x.x, acc.x); acc.y = fmaf(v, x.y, acc.y);
        acc.z = fmaf(v, x.z, acc.z); acc.w = fmaf(v, x.w, acc.w);
    }

    float* dst = (MODE == 0) ? d_e1 : (MODE == 1) ? d_e2 : d_e3;
    *reinterpret_cast<float4*>(dst + (size_t)r * D + c4) = acc;
}

// ---------------------------------------------------------------------------
// Final head: gather light embeddings, W_u/W_i matvecs, softmax, sigmoid, dot.
// ---------------------------------------------------------------------------
__global__ __launch_bounds__(64) void final_kernel(
    const float* __restrict__ embU, const float* __restrict__ embI,
    const float* __restrict__ wU,   const float* __restrict__ wI,
    const float* __restrict__ x1,   const float* __restrict__ x0,
    const int*   __restrict__ users,const int*   __restrict__ items,
    const int*   __restrict__ xij,  float*       __restrict__ out) {
    __shared__ float sWu[D * D];
    __shared__ float sWi[D * D];
    __shared__ float sa[D * 64];

    int tid = threadIdx.x;
    for (int i = tid; i < D * D; i += 64) {
        sWu[i] = wU[i];
        sWi[i] = wI[i];
    }
    __syncthreads();

    int b  = blockIdx.x * 64 + tid;
    int u  = users[b];
    int it = items[b];

    float vec[D];

    {
        const float* p0 = embU + (size_t)u * D;
        const float* p1 = d_e1 + (size_t)u * D;
        const float* p2 = d_e2 + (size_t)u * D;
        const float* p3 = d_e3 + (size_t)u * D;
#pragma unroll
        for (int d = 0; d < D; d++)
            vec[d] = 0.25f * (p0[d] + p1[d] + p2[d] + p3[d]);
    }

    float amax = -1e30f;
    for (int j = 0; j < D; j++) {
        const float* w = sWu + j * D;
        float a = 0.f;
#pragma unroll
        for (int d = 0; d < D; d++) a = fmaf(vec[d], w[d], a);
        sa[j * 64 + tid] = a;
        amax = fmaxf(amax, a);
    }
    float ssum = 0.f;
    for (int j = 0; j < D; j++) {
        float ex = __expf(sa[j * 64 + tid] - amax);
        sa[j * 64 + tid] = ex;
        ssum += ex;
    }
    float scale = 0.5f / ssum;   // (1 - hx) * softmax

    {
        size_t ir = (size_t)(N_USERS + it) * D;
        const float* q0 = embI + (size_t)it * D;
#pragma unroll
        for (int d = 0; d < D; d++)
            vec[d] = 0.25f * (q0[d] + d_e1[ir + d] + d_e2[ir + d] + d_e3[ir + d]);
    }

    float res = 0.f;
    for (int j = 0; j < D; j++) {
        const float* w = sWi + j * D;
        float a = 0.f;
#pragma unroll
        for (int d = 0; d < D; d++) a = fmaf(vec[d], w[d], a);
        float sg = 1.f / (1.f + __expf(-a));
        res += sa[j * 64 + tid] * scale * sg;
    }

    float xe = (xij[b] > 0) ? x1[it] : x0[it];
    res += 0.5f * (1.f / (1.f + __expf(-xe)));

    out[b] = res;
}

// ---------------------------------------------------------------------------
extern "C" void kernel_launch(void* const* d_in, const int* in_sizes, int n_in,
                              void* d_out, int out_size) {
    const float* embU  = (const float*)d_in[0];
    const float* embI  = (const float*)d_in[1];
    const float* wU    = (const float*)d_in[2];
    const float* wI    = (const float*)d_in[3];
    const float* x1    = (const float*)d_in[4];
    const float* x0    = (const float*)d_in[5];
    const float* gval  = (const float*)d_in[6];
    const int*   grow  = (const int*)d_in[7];
    const int*   gcol  = (const int*)d_in[8];
    const int*   users = (const int*)d_in[9];
    const int*   items = (const int*)d_in[10];
    const int*   xij   = (const int*)d_in[11];
    float*       out   = (float*)d_out;

    (void)in_sizes; (void)n_in; (void)out_size;

    // CSR build
    reset_kernel<<<(NTOT + 255) / 256, 256>>>();
    mark_kernel<<<(2 * BSZ + 255) / 256, 256>>>(users, items);
    hist_kernel<<<(NNZ + 255) / 256, 256>>>(grow);
    scan1_kernel<<<NBLK, 256>>>();
    scan2_kernel<<<1, 256>>>();
    scan3_kernel<<<(NTOT + 1 + 255) / 256, 256>>>();
    scatter_kernel<<<(NNZ + 255) / 256, 256>>>(grow, gcol, gval);

    // Three row-parallel SpMM layers (16 lanes per row)
    const unsigned total  = (unsigned)NTOT * 16u;
    const unsigned blocks = (total + 255) / 256;
    spmm_csr_kernel<0><<<blocks, 256>>>(embU, embI);
    spmm_csr_kernel<1><<<blocks, 256>>>(embU, embI);
    spmm_csr_kernel<2><<<blocks, 256>>>(embU, embI);

    // Final head
    final_kernel<<<BSZ / 64, 64>>>(embU, embI, wU, wI, x1, x0,
                                   users, items, xij, out);
}